// round 14
// baseline (speedup 1.0000x reference)
#include <cuda_runtime.h>
#include <math.h>

// ---------------------------------------------------------------------------
// GatingNeuralAdaptiveBias — single fused persistent kernel.
//   out(x0, sigma) tabulated 257 x 1025 fp32 -> per-pixel = 1 bilinear.
//   Phase A: node e-rows (warp-per-node, shuffle GEMMs) + sidecars + gate g
//   Phase B: coarse w0(x0,sigma) 129 x 257 (sigmoid applied)
//   Phase C: out2d = closed-form LN( w0 e0 + w1 e1 ) . c1 + sbw
//   Phase D: main — x0, diamond-sigma -> bilinear(out2d)
// Phases separated by software grid barriers (co-residency guaranteed:
// 444 blocks launched < 592 = 148 SMs x 4 resident @ launch_bounds(256,4)).
// ---------------------------------------------------------------------------

typedef unsigned int uint;

#define PI_F 3.14159265358979323846f
#define NE0 256
#define NE1 1024
#define NG0 128
#define NG1 256
#define OST 1025
#define E1TS 1056
#define NBLK 444

__device__ __align__(16) float g_e0f[260 * 64];
__device__ __align__(16) float g_e1t[64 * E1TS];
__device__ __align__(16) float g_s0[260], g_q0[260], g_d0[260];
__device__ __align__(16) float g_s1[1032], g_q1[1032], g_d1[1032];
__device__ __align__(16) float g_g0c[132 * 64];
__device__ __align__(16) float g_g1c[260 * 64];
__device__ __align__(16) float g_w2d[129 * 257 + 8];
__device__ __align__(16) float g_out2d[257 * OST + 8];
// g_pre: [0..63] wd ; 64 itemp ; 65 sbw ; 66 bg2d ; 67 c1s
__device__ __align__(16) float g_pre[68];
__device__ unsigned int g_bar;

#define NB_E0 257
#define NB_E1 1025
#define NB_G0 129
#define NB_G1 257
#define NB_TOT (NB_E0 + NB_E1 + NB_G0 + NB_G1)   // 1668

__device__ __forceinline__ float silu_acc(float v) { return v / (1.0f + expf(-v)); }

__device__ __forceinline__ void grid_sync() {
    __syncthreads();
    if (threadIdx.x == 0) {
        __threadfence();
        const unsigned old = atomicAdd(&g_bar, 1u);
        const unsigned target = (old / NBLK + 1u) * NBLK;
        volatile unsigned* p = &g_bar;
        while ((int)(*p - target) < 0) { }
        __threadfence();
    }
    __syncthreads();
}

// theta at a sigma node; sigma in [0,4]; node 0 -> -pi.
__device__ __forceinline__ float theta_from_sigma(float sigma, int ent) {
    if (ent == 0) return -PI_F;
    const float tau = (sigma >= 2.0f) ? sigma - 2.0f : sigma + 2.0f;
    float x, y;
    if      (tau < 1.0f) { x = 1.0f - tau; y = tau; }
    else if (tau < 2.0f) { x = 1.0f - tau; y = 2.0f - tau; }
    else if (tau < 3.0f) { x = tau - 3.0f; y = 2.0f - tau; }
    else                 { x = tau - 3.0f; y = tau - 4.0f; }
    return atan2f(y, x);
}

__global__ void __launch_bounds__(256, 4)
gnab_all(const float* __restrict__ coords, const float* __restrict__ cost,
         const float* __restrict__ lsc,
         const float* __restrict__ W1,  const float* __restrict__ b1,
         const float* __restrict__ W2,  const float* __restrict__ b2,
         const float* __restrict__ fg,  const float* __restrict__ fb,
         const float* __restrict__ Wg1, const float* __restrict__ bg1,
         const float* __restrict__ Wg2, const float* __restrict__ bg2,
         const float* __restrict__ temp,
         const float* __restrict__ lng, const float* __restrict__ lnb,
         const float* __restrict__ Wo,  const float* __restrict__ bo,
         float* __restrict__ out)
{
    const int tid  = threadIdx.x;
    const int blk  = blockIdx.x;
    const int lane = tid & 31;
    const int wid  = tid >> 5;

    __shared__ float s_wd[64];
    __shared__ __align__(16) float se0[256];
    __shared__ float sS[12];

    // ======================= Phase A: nodes + consts =======================
    if (blk == NBLK - 1) {
        if (tid < 64) g_pre[tid] = Wg2[2 * tid] - Wg2[2 * tid + 1];
        if (tid == 64) {
            float s = bo[0], cs = 0.0f;
            for (int k = 0; k < 64; k++) { s += lnb[k] * Wo[k]; cs += lng[k] * Wo[k]; }
            g_pre[64] = expf(-temp[0]);
            g_pre[65] = s;
            g_pre[66] = bg2[0] - bg2[1];
            g_pre[67] = cs;
        }
    }

    const int node = blk * 8 + wid;
    if (node < NB_TOT) {
        int mode, ch, ent;
        if      (node < NB_E0)                  { mode = 0; ch = 0; ent = node; }
        else if (node < NB_E0 + NB_E1)          { mode = 0; ch = 1; ent = node - NB_E0; }
        else if (node < NB_E0 + NB_E1 + NB_G0)  { mode = 1; ch = 0; ent = node - NB_E0 - NB_E1; }
        else                                    { mode = 1; ch = 1; ent = node - NB_E0 - NB_E1 - NB_G0; }

        float x;
        if (ch == 0) x = (float)ent * (mode ? (1.0f / NG0) : (1.0f / NE0));
        else {
            const float sig = (float)ent * (mode ? (4.0f / NG1) : (4.0f / NE1));
            x = theta_from_sigma(sig, ent);
        }
        const float sc = expf(lsc[ch]);

        float ft[9];
        ft[0] = x * sc;
        #pragma unroll
        for (int q = 0; q < 4; q++) {
            float s, c;
            sincosf(x * (float)(1 << q), &s, &c);
            ft[1 + 2 * q] = s * sc;
            ft[2 + 2 * q] = c * sc;
        }

        const int dlo = lane, dhi = lane + 32;
        float z0 = b1[dlo], z1 = b1[dhi];
        #pragma unroll
        for (int f = 0; f < 9; f++) {
            z0 = fmaf(ft[f], W1[f * 64 + dlo], z0);
            z1 = fmaf(ft[f], W1[f * 64 + dhi], z1);
        }
        const float h0 = silu_acc(z0);
        const float h1 = silu_acc(z1);

        float ea = 0.0f, eb = 0.0f;
        #pragma unroll 8
        for (int j = 0; j < 32; j++) {
            const float hj = __shfl_sync(0xFFFFFFFFu, h0, j);
            ea = fmaf(hj, W2[j * 64 + dlo], ea);
            eb = fmaf(hj, W2[j * 64 + dhi], eb);
        }
        #pragma unroll 8
        for (int j = 0; j < 32; j++) {
            const float hj = __shfl_sync(0xFFFFFFFFu, h1, j);
            ea = fmaf(hj, W2[(32 + j) * 64 + dlo], ea);
            eb = fmaf(hj, W2[(32 + j) * 64 + dhi], eb);
        }
        const float elo = fmaf(ea + b2[dlo], fg[ch * 64 + dlo], fb[ch * 64 + dlo]);
        const float ehi = fmaf(eb + b2[dhi], fg[ch * 64 + dhi], fb[ch * 64 + dhi]);

        if (mode == 0) {
            if (ch) { g_e1t[dlo * E1TS + ent] = elo; g_e1t[dhi * E1TS + ent] = ehi; }
            else    { g_e0f[ent * 64 + dlo]  = elo; g_e0f[ent * 64 + dhi]  = ehi; }
            const float c1lo = lng[dlo] * Wo[dlo];
            const float c1hi = lng[dhi] * Wo[dhi];
            float s = elo + ehi;
            float q = elo * elo + ehi * ehi;
            float d = elo * c1lo + ehi * c1hi;
            #pragma unroll
            for (int o = 16; o > 0; o >>= 1) {
                s += __shfl_xor_sync(0xFFFFFFFFu, s, o);
                q += __shfl_xor_sync(0xFFFFFFFFu, q, o);
                d += __shfl_xor_sync(0xFFFFFFFFu, d, o);
            }
            if (lane == 0) {
                if (ch) { g_s1[ent] = s; g_q1[ent] = q; g_d1[ent] = d; }
                else    { g_s0[ent] = s; g_q0[ent] = q; g_d0[ent] = d; }
            }
        } else {
            float glo = (ch == 0) ? bg1[dlo] : 0.0f;
            float ghi = (ch == 0) ? bg1[dhi] : 0.0f;
            #pragma unroll 8
            for (int k = 0; k < 32; k++) {
                const float ek = __shfl_sync(0xFFFFFFFFu, elo, k);
                glo = fmaf(ek, Wg1[(ch * 64 + k) * 64 + dlo], glo);
                ghi = fmaf(ek, Wg1[(ch * 64 + k) * 64 + dhi], ghi);
            }
            #pragma unroll 8
            for (int k = 0; k < 32; k++) {
                const float ek = __shfl_sync(0xFFFFFFFFu, ehi, k);
                glo = fmaf(ek, Wg1[(ch * 64 + 32 + k) * 64 + dlo], glo);
                ghi = fmaf(ek, Wg1[(ch * 64 + 32 + k) * 64 + dhi], ghi);
            }
            float* dst = ch ? g_g1c : g_g0c;
            dst[ent * 64 + dlo] = glo;
            dst[ent * 64 + dhi] = ghi;
        }
    }
    grid_sync();

    // ======================= Phase B: coarse w0 table ======================
    if (tid < 64) s_wd[tid] = g_pre[tid];
    __syncthreads();
    {
        const int idx = blk * 256 + tid;
        if (idx < 129 * 257) {
            const int i0 = idx / 257;
            const int i1 = idx - i0 * 257;
            const float4* a = reinterpret_cast<const float4*>(&g_g0c[i0 * 64]);
            const float4* b = reinterpret_cast<const float4*>(&g_g1c[i1 * 64]);
            float acc = g_pre[66];
            #pragma unroll 4
            for (int k = 0; k < 16; k++) {
                const float4 av = __ldg(&a[k]);
                const float4 bv = __ldg(&b[k]);
                acc = fmaf(silu_acc(av.x + bv.x), s_wd[4 * k],     acc);
                acc = fmaf(silu_acc(av.y + bv.y), s_wd[4 * k + 1], acc);
                acc = fmaf(silu_acc(av.z + bv.z), s_wd[4 * k + 2], acc);
                acc = fmaf(silu_acc(av.w + bv.w), s_wd[4 * k + 3], acc);
            }
            g_w2d[idx] = 1.0f / (1.0f + expf(-acc * g_pre[64]));
        }
    }
    grid_sync();

    // ======================= Phase C: out2d build ==========================
    if (blk < 325) {
        const int i0seg = blk / 5;
        const int i1seg = blk - i0seg * 5;
        {
            const int r = tid >> 6, k = tid & 63;
            const int i0 = i0seg * 4 + r;
            se0[tid] = (i0 <= NE0) ? g_e0f[i0 * 64 + k] : 0.0f;
        }
        if (tid < 4) {
            const int i0 = i0seg * 4 + tid;
            const int ic = (i0 <= NE0) ? i0 : NE0;
            sS[tid] = g_s0[ic];  sS[4 + tid] = g_q0[ic];  sS[8 + tid] = g_d0[ic];
        }
        __syncthreads();

        const int i1 = i1seg * 256 + tid;
        if (i1 <= NE1) {
            float X[4] = {0, 0, 0, 0};
            #pragma unroll 8
            for (int k = 0; k < 64; k++) {
                const float a = __ldg(&g_e1t[k * E1TS + i1]);
                X[0] = fmaf(se0[k],       a, X[0]);
                X[1] = fmaf(se0[64 + k],  a, X[1]);
                X[2] = fmaf(se0[128 + k], a, X[2]);
                X[3] = fmaf(se0[192 + k], a, X[3]);
            }
            const float sbw = g_pre[65];
            const float c1s = g_pre[67];
            const float s1 = g_s1[i1], q1 = g_q1[i1], d1 = g_d1[i1];

            int   i1c = i1 >> 2;
            float f1c = (float)(i1 & 3) * 0.25f;
            if (i1c > NG1 - 1) { i1c = NG1 - 1; f1c = 1.0f; }

            #pragma unroll
            for (int r = 0; r < 4; r++) {
                const int i0 = i0seg * 4 + r;
                if (i0 > NE0) break;
                int   i0c = i0 >> 1;
                float f0c = (float)(i0 & 1) * 0.5f;
                if (i0c > NG0 - 1) { i0c = NG0 - 1; f0c = 1.0f; }

                const float* W = &g_w2d[i0c * 257 + i1c];
                const float t00 = __ldg(W),       t01 = __ldg(W + 1);
                const float t10 = __ldg(W + 257), t11 = __ldg(W + 258);
                const float la = fmaf(f1c, t01 - t00, t00);
                const float lb = fmaf(f1c, t11 - t10, t10);
                const float w0 = fmaf(f0c, lb - la, la);
                const float w1 = 1.0f - w0;

                const float S = w0 * sS[r] + w1 * s1;
                const float Q = w0 * w0 * sS[4 + r] + 2.0f * w0 * w1 * X[r] + w1 * w1 * q1;
                const float D = w0 * sS[8 + r] + w1 * d1;
                const float mu   = S * (1.0f / 64.0f);
                const float var  = Q * (1.0f / 64.0f) - mu * mu;
                const float rstd = rsqrtf(var + 1e-5f);
                g_out2d[i0 * OST + i1] = fmaf((D - mu * c1s), rstd, sbw);
            }
        }
    }
    grid_sync();

    // ======================= Phase D: main lookups =========================
    for (int p = blk * 256 + tid; p < 524288; p += NBLK * 256) {
        const int row = p >> 8;
        const int j   = p & 255;
        const int b   = row >> 8;
        const int i   = row & 255;

        const float x0 = __ldg(&cost[p]);
        const float2 ci = __ldg(reinterpret_cast<const float2*>(&coords[(b * 256 + i) * 2]));
        const float2 cj = __ldg(reinterpret_cast<const float2*>(&coords[(b * 256 + j) * 2]));
        const float dx = ci.x - cj.x;
        const float dy = ci.y - cj.y;

        const float ax = fabsf(dx), ay = fabsf(dy);
        const float den = ax + ay;
        const float t = (den > 0.0f) ? __fdividef(ay, den) : 0.0f;
        float tau;
        if (dx >= 0.0f) tau = (dy >= 0.0f) ? t : 4.0f - t;
        else            tau = (dy >= 0.0f) ? 2.0f - t : 2.0f + t;
        const float sigma = (tau > 2.0f) ? tau - 2.0f : tau + 2.0f;

        float u0 = x0 * (float)NE0;
        int i0 = (int)u0;
        i0 = (i0 < 0) ? 0 : ((i0 > NE0 - 1) ? NE0 - 1 : i0);
        const float f0 = u0 - (float)i0;

        float u1 = sigma * ((float)NE1 * 0.25f);
        int i1 = (int)u1;
        i1 = (i1 < 0) ? 0 : ((i1 > NE1 - 1) ? NE1 - 1 : i1);
        const float f1 = u1 - (float)i1;

        const float* R = &g_out2d[i0 * OST + i1];
        const float t00 = __ldg(R);
        const float t01 = __ldg(R + 1);
        const float t10 = __ldg(R + OST);
        const float t11 = __ldg(R + OST + 1);
        const float la = fmaf(f1, t01 - t00, t00);
        const float lb = fmaf(f1, t11 - t10, t10);
        out[p] = fmaf(f0, lb - la, la);
    }
}

// ============================ launch =======================================
extern "C" void kernel_launch(void* const* d_in, const int* in_sizes, int n_in,
                              void* d_out, int out_size)
{
    const float* coords = (const float*)d_in[0];
    const float* cost   = (const float*)d_in[1];
    const float* lsc    = (const float*)d_in[2];
    const float* W1     = (const float*)d_in[3];
    const float* b1     = (const float*)d_in[4];
    const float* W2     = (const float*)d_in[5];
    const float* b2     = (const float*)d_in[6];
    const float* fg     = (const float*)d_in[7];
    const float* fb     = (const float*)d_in[8];
    const float* Wg1    = (const float*)d_in[9];
    const float* bg1    = (const float*)d_in[10];
    const float* Wg2    = (const float*)d_in[11];
    const float* bg2    = (const float*)d_in[12];
    const float* temp   = (const float*)d_in[13];
    const float* lng    = (const float*)d_in[14];
    const float* lnb    = (const float*)d_in[15];
    const float* Wo     = (const float*)d_in[16];
    const float* bo     = (const float*)d_in[17];
    float* out          = (float*)d_out;

    gnab_all<<<NBLK, 256>>>(coords, cost, lsc, W1, b1, W2, b2, fg, fb,
                            Wg1, bg1, Wg2, bg2, temp, lng, lnb, Wo, bo, out);
}

// round 15
// speedup vs baseline: 1.0072x; 1.0072x over previous
#include <cuda_runtime.h>
#include <math.h>

// ---------------------------------------------------------------------------
// GatingNeuralAdaptiveBias — hybrid: fused persistent SETUP + big-grid MAIN.
//   out(x0, sigma) tabulated 257 x 1025 fp32 -> per-pixel = 1 bilinear.
//   K1 (209 blocks, persistent, 2 grid barriers):
//     Phase A: node e-rows (warp-per-node shuffle GEMMs) + sidecars + gate g
//     Phase B: coarse w0(x0,sigma) 129 x 257 (sigmoid applied)
//     Phase C: out2d = closed-form LN( w0 e0 + w1 e1 ) . c1 + sbw
//   K2 (2048 blocks): x0, diamond-sigma -> bilinear(out2d).
// ---------------------------------------------------------------------------

typedef unsigned int uint;

#define PI_F 3.14159265358979323846f
#define NE0 256
#define NE1 1024
#define NG0 128
#define NG1 256
#define OST 1025
#define E1TS 1056
#define NBLK_S 209

__device__ __align__(16) float g_e0f[260 * 64];
__device__ __align__(16) float g_e1t[64 * E1TS];
__device__ __align__(16) float g_s0[260], g_q0[260], g_d0[260];
__device__ __align__(16) float g_s1[1032], g_q1[1032], g_d1[1032];
__device__ __align__(16) float g_g0c[132 * 64];
__device__ __align__(16) float g_g1c[260 * 64];
__device__ __align__(16) float g_w2d[129 * 257 + 8];
__device__ __align__(16) float g_out2d[257 * OST + 8];
// g_pre: [0..63] wd ; 64 itemp ; 65 sbw ; 66 bg2d ; 67 c1s
__device__ __align__(16) float g_pre[68];
__device__ unsigned int g_bar;

#define NB_E0 257
#define NB_E1 1025
#define NB_G0 129
#define NB_G1 257
#define NB_TOT (NB_E0 + NB_E1 + NB_G0 + NB_G1)   // 1668

__device__ __forceinline__ float silu_acc(float v) { return v / (1.0f + expf(-v)); }

__device__ __forceinline__ void grid_sync() {
    __syncthreads();
    if (threadIdx.x == 0) {
        __threadfence();
        const unsigned old = atomicAdd(&g_bar, 1u);
        const unsigned target = (old / NBLK_S + 1u) * NBLK_S;
        volatile unsigned* p = &g_bar;
        while ((int)(*p - target) < 0) { }
        __threadfence();
    }
    __syncthreads();
}

// theta at a sigma node; sigma in [0,4]; node 0 -> -pi.
__device__ __forceinline__ float theta_from_sigma(float sigma, int ent) {
    if (ent == 0) return -PI_F;
    const float tau = (sigma >= 2.0f) ? sigma - 2.0f : sigma + 2.0f;
    float x, y;
    if      (tau < 1.0f) { x = 1.0f - tau; y = tau; }
    else if (tau < 2.0f) { x = 1.0f - tau; y = 2.0f - tau; }
    else if (tau < 3.0f) { x = tau - 3.0f; y = 2.0f - tau; }
    else                 { x = tau - 3.0f; y = tau - 4.0f; }
    return atan2f(y, x);
}

// ======================= K1: fused setup (persistent) ======================
__global__ void __launch_bounds__(256, 4)
k_setup(const float* __restrict__ lsc,
        const float* __restrict__ W1,  const float* __restrict__ b1,
        const float* __restrict__ W2,  const float* __restrict__ b2,
        const float* __restrict__ fg,  const float* __restrict__ fb,
        const float* __restrict__ Wg1, const float* __restrict__ bg1,
        const float* __restrict__ Wg2, const float* __restrict__ bg2,
        const float* __restrict__ temp,
        const float* __restrict__ lng, const float* __restrict__ lnb,
        const float* __restrict__ Wo,  const float* __restrict__ bo)
{
    const int tid  = threadIdx.x;
    const int blk  = blockIdx.x;
    const int lane = tid & 31;
    const int wid  = tid >> 5;

    __shared__ float s_wd[64];
    __shared__ __align__(16) float se0[256];
    __shared__ float sS[12];

    // ---------------- Phase A: nodes + consts ----------------
    if (blk == NBLK_S - 1) {
        if (tid < 64) g_pre[tid] = Wg2[2 * tid] - Wg2[2 * tid + 1];
        if (tid == 64) {
            float s = bo[0], cs = 0.0f;
            for (int k = 0; k < 64; k++) { s += lnb[k] * Wo[k]; cs += lng[k] * Wo[k]; }
            g_pre[64] = expf(-temp[0]);
            g_pre[65] = s;
            g_pre[66] = bg2[0] - bg2[1];
            g_pre[67] = cs;
        }
    }

    const int node = blk * 8 + wid;
    if (node < NB_TOT) {
        int mode, ch, ent;
        if      (node < NB_E0)                  { mode = 0; ch = 0; ent = node; }
        else if (node < NB_E0 + NB_E1)          { mode = 0; ch = 1; ent = node - NB_E0; }
        else if (node < NB_E0 + NB_E1 + NB_G0)  { mode = 1; ch = 0; ent = node - NB_E0 - NB_E1; }
        else                                    { mode = 1; ch = 1; ent = node - NB_E0 - NB_E1 - NB_G0; }

        float x;
        if (ch == 0) x = (float)ent * (mode ? (1.0f / NG0) : (1.0f / NE0));
        else {
            const float sig = (float)ent * (mode ? (4.0f / NG1) : (4.0f / NE1));
            x = theta_from_sigma(sig, ent);
        }
        const float sc = expf(lsc[ch]);

        float ft[9];
        ft[0] = x * sc;
        #pragma unroll
        for (int q = 0; q < 4; q++) {
            float s, c;
            sincosf(x * (float)(1 << q), &s, &c);
            ft[1 + 2 * q] = s * sc;
            ft[2 + 2 * q] = c * sc;
        }

        const int dlo = lane, dhi = lane + 32;
        float z0 = b1[dlo], z1 = b1[dhi];
        #pragma unroll
        for (int f = 0; f < 9; f++) {
            z0 = fmaf(ft[f], W1[f * 64 + dlo], z0);
            z1 = fmaf(ft[f], W1[f * 64 + dhi], z1);
        }
        const float h0 = silu_acc(z0);
        const float h1 = silu_acc(z1);

        float ea = 0.0f, eb = 0.0f;
        #pragma unroll 8
        for (int j = 0; j < 32; j++) {
            const float hj = __shfl_sync(0xFFFFFFFFu, h0, j);
            ea = fmaf(hj, W2[j * 64 + dlo], ea);
            eb = fmaf(hj, W2[j * 64 + dhi], eb);
        }
        #pragma unroll 8
        for (int j = 0; j < 32; j++) {
            const float hj = __shfl_sync(0xFFFFFFFFu, h1, j);
            ea = fmaf(hj, W2[(32 + j) * 64 + dlo], ea);
            eb = fmaf(hj, W2[(32 + j) * 64 + dhi], eb);
        }
        const float elo = fmaf(ea + b2[dlo], fg[ch * 64 + dlo], fb[ch * 64 + dlo]);
        const float ehi = fmaf(eb + b2[dhi], fg[ch * 64 + dhi], fb[ch * 64 + dhi]);

        if (mode == 0) {
            if (ch) { g_e1t[dlo * E1TS + ent] = elo; g_e1t[dhi * E1TS + ent] = ehi; }
            else    { g_e0f[ent * 64 + dlo]  = elo; g_e0f[ent * 64 + dhi]  = ehi; }
            const float c1lo = lng[dlo] * Wo[dlo];
            const float c1hi = lng[dhi] * Wo[dhi];
            float s = elo + ehi;
            float q = elo * elo + ehi * ehi;
            float d = elo * c1lo + ehi * c1hi;
            #pragma unroll
            for (int o = 16; o > 0; o >>= 1) {
                s += __shfl_xor_sync(0xFFFFFFFFu, s, o);
                q += __shfl_xor_sync(0xFFFFFFFFu, q, o);
                d += __shfl_xor_sync(0xFFFFFFFFu, d, o);
            }
            if (lane == 0) {
                if (ch) { g_s1[ent] = s; g_q1[ent] = q; g_d1[ent] = d; }
                else    { g_s0[ent] = s; g_q0[ent] = q; g_d0[ent] = d; }
            }
        } else {
            float glo = (ch == 0) ? bg1[dlo] : 0.0f;
            float ghi = (ch == 0) ? bg1[dhi] : 0.0f;
            #pragma unroll 8
            for (int k = 0; k < 32; k++) {
                const float ek = __shfl_sync(0xFFFFFFFFu, elo, k);
                glo = fmaf(ek, Wg1[(ch * 64 + k) * 64 + dlo], glo);
                ghi = fmaf(ek, Wg1[(ch * 64 + k) * 64 + dhi], ghi);
            }
            #pragma unroll 8
            for (int k = 0; k < 32; k++) {
                const float ek = __shfl_sync(0xFFFFFFFFu, ehi, k);
                glo = fmaf(ek, Wg1[(ch * 64 + 32 + k) * 64 + dlo], glo);
                ghi = fmaf(ek, Wg1[(ch * 64 + 32 + k) * 64 + dhi], ghi);
            }
            float* dst = ch ? g_g1c : g_g0c;
            dst[ent * 64 + dlo] = glo;
            dst[ent * 64 + dhi] = ghi;
        }
    }
    grid_sync();

    // ---------------- Phase B: coarse w0 table ----------------
    if (tid < 64) s_wd[tid] = g_pre[tid];
    __syncthreads();
    {
        const int idx = blk * 256 + tid;     // 209*256 = 53504 > 33153: one pass
        if (idx < 129 * 257) {
            const int i0 = idx / 257;
            const int i1 = idx - i0 * 257;
            const float4* a = reinterpret_cast<const float4*>(&g_g0c[i0 * 64]);
            const float4* b = reinterpret_cast<const float4*>(&g_g1c[i1 * 64]);
            float acc = g_pre[66];
            #pragma unroll 4
            for (int k = 0; k < 16; k++) {
                const float4 av = __ldg(&a[k]);
                const float4 bv = __ldg(&b[k]);
                acc = fmaf(silu_acc(av.x + bv.x), s_wd[4 * k],     acc);
                acc = fmaf(silu_acc(av.y + bv.y), s_wd[4 * k + 1], acc);
                acc = fmaf(silu_acc(av.z + bv.z), s_wd[4 * k + 2], acc);
                acc = fmaf(silu_acc(av.w + bv.w), s_wd[4 * k + 3], acc);
            }
            g_w2d[idx] = 1.0f / (1.0f + expf(-acc * g_pre[64]));
        }
    }
    grid_sync();

    // ---------------- Phase C: out2d build ----------------
    for (int chunk = blk; chunk < 325; chunk += NBLK_S) {
        const int i0seg = chunk / 5;
        const int i1seg = chunk - i0seg * 5;
        __syncthreads();
        {
            const int r = tid >> 6, k = tid & 63;
            const int i0 = i0seg * 4 + r;
            se0[tid] = (i0 <= NE0) ? g_e0f[i0 * 64 + k] : 0.0f;
        }
        if (tid < 4) {
            const int i0 = i0seg * 4 + tid;
            const int ic = (i0 <= NE0) ? i0 : NE0;
            sS[tid] = g_s0[ic];  sS[4 + tid] = g_q0[ic];  sS[8 + tid] = g_d0[ic];
        }
        __syncthreads();

        const int i1 = i1seg * 256 + tid;
        if (i1 > NE1) continue;

        float X[4] = {0, 0, 0, 0};
        #pragma unroll 8
        for (int k = 0; k < 64; k++) {
            const float a = __ldg(&g_e1t[k * E1TS + i1]);
            X[0] = fmaf(se0[k],       a, X[0]);
            X[1] = fmaf(se0[64 + k],  a, X[1]);
            X[2] = fmaf(se0[128 + k], a, X[2]);
            X[3] = fmaf(se0[192 + k], a, X[3]);
        }
        const float sbw = g_pre[65];
        const float c1s = g_pre[67];
        const float s1 = g_s1[i1], q1 = g_q1[i1], d1 = g_d1[i1];

        int   i1c = i1 >> 2;
        float f1c = (float)(i1 & 3) * 0.25f;
        if (i1c > NG1 - 1) { i1c = NG1 - 1; f1c = 1.0f; }

        #pragma unroll
        for (int r = 0; r < 4; r++) {
            const int i0 = i0seg * 4 + r;
            if (i0 > NE0) break;
            int   i0c = i0 >> 1;
            float f0c = (float)(i0 & 1) * 0.5f;
            if (i0c > NG0 - 1) { i0c = NG0 - 1; f0c = 1.0f; }

            const float* W = &g_w2d[i0c * 257 + i1c];
            const float t00 = __ldg(W),       t01 = __ldg(W + 1);
            const float t10 = __ldg(W + 257), t11 = __ldg(W + 258);
            const float la = fmaf(f1c, t01 - t00, t00);
            const float lb = fmaf(f1c, t11 - t10, t10);
            const float w0 = fmaf(f0c, lb - la, la);
            const float w1 = 1.0f - w0;

            const float S = w0 * sS[r] + w1 * s1;
            const float Q = w0 * w0 * sS[4 + r] + 2.0f * w0 * w1 * X[r] + w1 * w1 * q1;
            const float D = w0 * sS[8 + r] + w1 * d1;
            const float mu   = S * (1.0f / 64.0f);
            const float var  = Q * (1.0f / 64.0f) - mu * mu;
            const float rstd = rsqrtf(var + 1e-5f);
            g_out2d[i0 * OST + i1] = fmaf((D - mu * c1s), rstd, sbw);
        }
    }
}

// ======================= K2: main — bilinear per pixel =====================
__global__ void __launch_bounds__(256)
gnab_main(const float* __restrict__ coords,
          const float* __restrict__ cost,
          float* __restrict__ out)
{
    const int row = blockIdx.x;        // b*256 + i
    const int j   = threadIdx.x;
    const int b   = row >> 8;
    const int i   = row & 255;
    const int pixel = row * 256 + j;

    const float x0 = __ldg(&cost[pixel]);
    const float2 ci = __ldg(reinterpret_cast<const float2*>(&coords[(b * 256 + i) * 2]));
    const float2 cj = __ldg(reinterpret_cast<const float2*>(&coords[(b * 256 + j) * 2]));
    const float dx = ci.x - cj.x;
    const float dy = ci.y - cj.y;

    const float ax = fabsf(dx), ay = fabsf(dy);
    const float den = ax + ay;
    const float t = (den > 0.0f) ? __fdividef(ay, den) : 0.0f;
    float tau;
    if (dx >= 0.0f) tau = (dy >= 0.0f) ? t : 4.0f - t;
    else            tau = (dy >= 0.0f) ? 2.0f - t : 2.0f + t;
    const float sigma = (tau > 2.0f) ? tau - 2.0f : tau + 2.0f;

    float u0 = x0 * (float)NE0;
    int i0 = (int)u0;
    i0 = (i0 < 0) ? 0 : ((i0 > NE0 - 1) ? NE0 - 1 : i0);
    const float f0 = u0 - (float)i0;

    float u1 = sigma * ((float)NE1 * 0.25f);
    int i1 = (int)u1;
    i1 = (i1 < 0) ? 0 : ((i1 > NE1 - 1) ? NE1 - 1 : i1);
    const float f1 = u1 - (float)i1;

    const float* R = &g_out2d[i0 * OST + i1];
    const float t00 = __ldg(R);
    const float t01 = __ldg(R + 1);
    const float t10 = __ldg(R + OST);
    const float t11 = __ldg(R + OST + 1);
    const float la = fmaf(f1, t01 - t00, t00);
    const float lb = fmaf(f1, t11 - t10, t10);
    out[pixel] = fmaf(f0, lb - la, la);
}

// ============================ launch =======================================
extern "C" void kernel_launch(void* const* d_in, const int* in_sizes, int n_in,
                              void* d_out, int out_size)
{
    const float* coords = (const float*)d_in[0];
    const float* cost   = (const float*)d_in[1];
    const float* lsc    = (const float*)d_in[2];
    const float* W1     = (const float*)d_in[3];
    const float* b1     = (const float*)d_in[4];
    const float* W2     = (const float*)d_in[5];
    const float* b2     = (const float*)d_in[6];
    const float* fg     = (const float*)d_in[7];
    const float* fb     = (const float*)d_in[8];
    const float* Wg1    = (const float*)d_in[9];
    const float* bg1    = (const float*)d_in[10];
    const float* Wg2    = (const float*)d_in[11];
    const float* bg2    = (const float*)d_in[12];
    const float* temp   = (const float*)d_in[13];
    const float* lng    = (const float*)d_in[14];
    const float* lnb    = (const float*)d_in[15];
    const float* Wo     = (const float*)d_in[16];
    const float* bo     = (const float*)d_in[17];
    float* out          = (float*)d_out;

    k_setup<<<NBLK_S, 256>>>(lsc, W1, b1, W2, b2, fg, fb,
                             Wg1, bg1, Wg2, bg2, temp, lng, lnb, Wo, bo);
    gnab_main<<<2048, 256>>>(coords, cost, out);
}

// round 16
// speedup vs baseline: 1.2356x; 1.2267x over previous
#include <cuda_runtime.h>
#include <math.h>

// ---------------------------------------------------------------------------
// GatingNeuralAdaptiveBias — output-patch-table form.
//   out(x0, sigma) tabulated as 2x2 float4 PATCHES (256 x 1024, 4MB, L2):
//   main kernel = ONE LDG.128 + bilinear per pixel.
//   K1 k_nodes : e0 rows, E1 transposed, [s,q,d] sidecars, coarse gate g rows
//   K2 k_w2d   : coarse w0(x0,sigma) 65 x 129 (sigmoid applied)
//   K3 k_out2d : X = E0.E1 cross-dots + closed-form LN -> float4 patches
//   K4 main    : x0, diamond-sigma -> patch bilinear.
// ---------------------------------------------------------------------------

typedef unsigned int uint;

#define PI_F 3.14159265358979323846f
#define NE0 256
#define NE1 1024
#define NG0 64
#define NG1 128
#define E1TS 1056

__device__ __align__(16) float  g_e0f[260 * 64];
__device__ __align__(16) float  g_e1t[64 * E1TS];
__device__ __align__(16) float  g_s0[260], g_q0[260], g_d0[260];
__device__ __align__(16) float  g_s1[1032], g_q1[1032], g_d1[1032];
__device__ __align__(16) float  g_g0c[68 * 64];
__device__ __align__(16) float  g_g1c[132 * 64];
__device__ __align__(16) float  g_w2d[65 * 129 + 8];
__device__ __align__(16) float4 g_patch[256 * 1024];    // 4 MB
// g_pre: [0..63] wd ; 64 itemp ; 65 sbw ; 66 bg2d ; 67 c1s
__device__ __align__(16) float g_pre[68];

__device__ __forceinline__ float silu_f(float v) {
    return __fdividef(v, 1.0f + __expf(-v));
}

// theta at a sigma node; sigma in [0,4]; node 0 -> -pi.
__device__ __forceinline__ float theta_from_sigma(float sigma, int ent) {
    if (ent == 0) return -PI_F;
    const float tau = (sigma >= 2.0f) ? sigma - 2.0f : sigma + 2.0f;
    float x, y;
    if      (tau < 1.0f) { x = 1.0f - tau; y = tau; }
    else if (tau < 2.0f) { x = 1.0f - tau; y = 2.0f - tau; }
    else if (tau < 3.0f) { x = tau - 3.0f; y = 2.0f - tau; }
    else                 { x = tau - 3.0f; y = tau - 4.0f; }
    return atan2f(y, x);
}

// ==================== K1: node rows + sidecars + consts ====================
#define NB_E0 257
#define NB_E1 1025
#define NB_G0 65
#define NB_G1 129
#define NB_TOT (NB_E0 + NB_E1 + NB_G0 + NB_G1)   // 1476; grid = 1477
__global__ void __launch_bounds__(64)
k_nodes(const float* __restrict__ lsc,
        const float* __restrict__ W1,  const float* __restrict__ b1,
        const float* __restrict__ W2,  const float* __restrict__ b2,
        const float* __restrict__ fg,  const float* __restrict__ fb,
        const float* __restrict__ Wg1, const float* __restrict__ bg1,
        const float* __restrict__ Wg2, const float* __restrict__ bg2,
        const float* __restrict__ temp,
        const float* __restrict__ lng, const float* __restrict__ lnb,
        const float* __restrict__ Wo,  const float* __restrict__ bo)
{
    const int blk = blockIdx.x;
    const int tid = threadIdx.x;

    if (blk == NB_TOT) {                  // constants
        g_pre[tid] = Wg2[2 * tid] - Wg2[2 * tid + 1];
        if (tid == 0) {
            float s = bo[0], cs = 0.0f;
            for (int k = 0; k < 64; k++) { s += lnb[k] * Wo[k]; cs += lng[k] * Wo[k]; }
            g_pre[64] = expf(-temp[0]);
            g_pre[65] = s;
            g_pre[66] = bg2[0] - bg2[1];
            g_pre[67] = cs;
        }
        return;
    }

    __shared__ float sh[64];
    __shared__ float sred[6];

    int mode, ch, ent;
    if      (blk < NB_E0)                 { mode = 0; ch = 0; ent = blk; }
    else if (blk < NB_E0 + NB_E1)         { mode = 0; ch = 1; ent = blk - NB_E0; }
    else if (blk < NB_E0 + NB_E1 + NB_G0) { mode = 1; ch = 0; ent = blk - NB_E0 - NB_E1; }
    else                                  { mode = 1; ch = 1; ent = blk - NB_E0 - NB_E1 - NB_G0; }

    float x;
    if (ch == 0) x = (float)ent * (mode ? (1.0f / NG0) : (1.0f / NE0));
    else {
        const float sig = (float)ent * (mode ? (4.0f / NG1) : (4.0f / NE1));
        x = theta_from_sigma(sig, ent);
    }
    const float sc = expf(lsc[ch]);

    float ft[9];
    ft[0] = x * sc;
    #pragma unroll
    for (int q = 0; q < 4; q++) {
        float s, c;
        sincosf(x * (float)(1 << q), &s, &c);
        ft[1 + 2 * q] = s * sc;
        ft[2 + 2 * q] = c * sc;
    }

    float z = b1[tid];
    #pragma unroll
    for (int f = 0; f < 9; f++) z = fmaf(ft[f], W1[f * 64 + tid], z);
    sh[tid] = silu_f(z);
    __syncthreads();

    float e = 0.0f;
    #pragma unroll 8
    for (int j = 0; j < 64; j++) e = fmaf(sh[j], W2[j * 64 + tid], e);
    e = fmaf(e + b2[tid], fg[ch * 64 + tid], fb[ch * 64 + tid]);

    if (mode == 0) {
        if (ch) g_e1t[tid * E1TS + ent] = e;       // transposed
        else    g_e0f[ent * 64 + tid]  = e;
        const float c1d = lng[tid] * Wo[tid];
        float s = e, q = e * e, d = e * c1d;
        #pragma unroll
        for (int o = 16; o > 0; o >>= 1) {
            s += __shfl_xor_sync(0xFFFFFFFFu, s, o);
            q += __shfl_xor_sync(0xFFFFFFFFu, q, o);
            d += __shfl_xor_sync(0xFFFFFFFFu, d, o);
        }
        if ((tid & 31) == 0) {
            const int w = tid >> 5;
            sred[w * 3 + 0] = s;  sred[w * 3 + 1] = q;  sred[w * 3 + 2] = d;
        }
        __syncthreads();
        if (tid == 0) {
            if (ch) { g_s1[ent] = sred[0] + sred[3]; g_q1[ent] = sred[1] + sred[4]; g_d1[ent] = sred[2] + sred[5]; }
            else    { g_s0[ent] = sred[0] + sred[3]; g_q0[ent] = sred[1] + sred[4]; g_d0[ent] = sred[2] + sred[5]; }
        }
    } else {
        __syncthreads();
        sh[tid] = e;
        __syncthreads();
        float g = (ch == 0) ? bg1[tid] : 0.0f;
        #pragma unroll 8
        for (int k = 0; k < 64; k++)
            g = fmaf(sh[k], Wg1[(ch * 64 + k) * 64 + tid], g);
        (ch ? g_g1c : g_g0c)[ent * 64 + tid] = g;
    }
}

// ==================== K2: coarse w0 table (65 x 129) =======================
__global__ void __launch_bounds__(256)
k_w2d()
{
    __shared__ float s_wd[64];
    const int tid = threadIdx.x;
    if (tid < 64) s_wd[tid] = g_pre[tid];
    __syncthreads();

    const int idx = blockIdx.x * 256 + tid;
    if (idx >= 65 * 129) return;
    const int i0 = idx / 129;
    const int i1 = idx - i0 * 129;

    const float4* a = reinterpret_cast<const float4*>(&g_g0c[i0 * 64]);
    const float4* b = reinterpret_cast<const float4*>(&g_g1c[i1 * 64]);
    float acc = g_pre[66];
    #pragma unroll 4
    for (int k = 0; k < 16; k++) {
        const float4 av = __ldg(&a[k]);
        const float4 bv = __ldg(&b[k]);
        acc = fmaf(silu_f(av.x + bv.x), s_wd[4 * k],     acc);
        acc = fmaf(silu_f(av.y + bv.y), s_wd[4 * k + 1], acc);
        acc = fmaf(silu_f(av.z + bv.z), s_wd[4 * k + 2], acc);
        acc = fmaf(silu_f(av.w + bv.w), s_wd[4 * k + 3], acc);
    }
    g_w2d[idx] = __fdividef(1.0f, 1.0f + __expf(-acc * g_pre[64]));
}

// ==================== K3: patch build ======================================
// grid = 64 row-groups (4 patch-rows, 5 v-rows) x 5 col-segments.
// Warp owns 32 consecutive v-columns -> 31 patches; 8 warps = 248 cols/block.
__global__ void __launch_bounds__(256)
k_out2d()
{
    __shared__ __align__(16) float se0[5 * 64];
    __shared__ float sS[15];

    const int blk = blockIdx.x;
    const int rg  = blk / 5;
    const int seg = blk - rg * 5;
    const int tid = threadIdx.x;
    const int w   = tid >> 5;
    const int lane = tid & 31;

    for (int t = tid; t < 320; t += 256) {
        const int rr = t >> 6, k = t & 63;
        int i0v = rg * 4 + rr;
        if (i0v > NE0) i0v = NE0;
        se0[t] = g_e0f[i0v * 64 + k];
    }
    if (tid < 5) {
        int i0v = rg * 4 + tid;
        if (i0v > NE0) i0v = NE0;
        sS[tid] = g_s0[i0v];  sS[5 + tid] = g_q0[i0v];  sS[10 + tid] = g_d0[i0v];
    }
    __syncthreads();

    const int c  = seg * 248 + w * 31 + lane;      // v-column
    const int cc = (c > NE1) ? NE1 : c;

    float X[5] = {0, 0, 0, 0, 0};
    #pragma unroll 8
    for (int k = 0; k < 64; k++) {
        const float a = __ldg(&g_e1t[k * E1TS + cc]);
        X[0] = fmaf(se0[k],       a, X[0]);
        X[1] = fmaf(se0[64 + k],  a, X[1]);
        X[2] = fmaf(se0[128 + k], a, X[2]);
        X[3] = fmaf(se0[192 + k], a, X[3]);
        X[4] = fmaf(se0[256 + k], a, X[4]);
    }

    const float sbw = g_pre[65];
    const float c1s = g_pre[67];
    const float s1 = g_s1[cc], q1 = g_q1[cc], d1 = g_d1[cc];

    int   i1c = cc >> 3;                            // NE1/NG1 = 8
    float f1c = (float)(cc & 7) * 0.125f;
    if (i1c > NG1 - 1) { i1c = NG1 - 1; f1c = 1.0f; }

    float v[5];
    #pragma unroll
    for (int rr = 0; rr < 5; rr++) {
        int i0v = rg * 4 + rr;
        if (i0v > NE0) i0v = NE0;
        int   i0c = i0v >> 2;                       // NE0/NG0 = 4
        float f0c = (float)(i0v & 3) * 0.25f;
        if (i0c > NG0 - 1) { i0c = NG0 - 1; f0c = 1.0f; }

        const float* W = &g_w2d[i0c * 129 + i1c];
        const float t00 = __ldg(W),       t01 = __ldg(W + 1);
        const float t10 = __ldg(W + 129), t11 = __ldg(W + 130);
        const float la = fmaf(f1c, t01 - t00, t00);
        const float lb = fmaf(f1c, t11 - t10, t10);
        const float w0 = fmaf(f0c, lb - la, la);
        const float w1 = 1.0f - w0;

        const float S = w0 * sS[rr] + w1 * s1;
        const float Q = w0 * w0 * sS[5 + rr] + 2.0f * w0 * w1 * X[rr] + w1 * w1 * q1;
        const float D = w0 * sS[10 + rr] + w1 * d1;
        const float mu   = S * (1.0f / 64.0f);
        const float var  = Q * (1.0f / 64.0f) - mu * mu;
        const float rstd = rsqrtf(var + 1e-5f);
        v[rr] = fmaf((D - mu * c1s), rstd, sbw);
    }

    float vn[5];
    #pragma unroll
    for (int rr = 0; rr < 5; rr++)
        vn[rr] = __shfl_down_sync(0xFFFFFFFFu, v[rr], 1);

    if (lane < 31 && c < NE1) {
        const int pr0 = rg * 4;                      // patch rows pr0..pr0+3 <= 255
        #pragma unroll
        for (int rr = 0; rr < 4; rr++) {
            float4 P;
            P.x = v[rr];      P.y = vn[rr];
            P.z = v[rr + 1];  P.w = vn[rr + 1];
            g_patch[(pr0 + rr) * 1024 + c] = P;
        }
    }
}

// ==================== K4: main — one LDG.128 patch bilinear ================
__global__ void __launch_bounds__(256)
gnab_main(const float* __restrict__ coords,
          const float* __restrict__ cost,
          float* __restrict__ out)
{
    const int row = blockIdx.x;        // b*256 + i
    const int j   = threadIdx.x;
    const int b   = row >> 8;
    const int i   = row & 255;
    const int pixel = row * 256 + j;

    const float x0 = __ldg(&cost[pixel]);
    const float2 ci = __ldg(reinterpret_cast<const float2*>(&coords[(b * 256 + i) * 2]));
    const float2 cj = __ldg(reinterpret_cast<const float2*>(&coords[(b * 256 + j) * 2]));
    const float dx = ci.x - cj.x;
    const float dy = ci.y - cj.y;

    const float ax = fabsf(dx), ay = fabsf(dy);
    const float den = ax + ay;
    const float t = (den > 0.0f) ? __fdividef(ay, den) : 0.0f;
    float tau;
    if (dx >= 0.0f) tau = (dy >= 0.0f) ? t : 4.0f - t;
    else            tau = (dy >= 0.0f) ? 2.0f - t : 2.0f + t;
    const float sigma = (tau > 2.0f) ? tau - 2.0f : tau + 2.0f;

    float u0 = x0 * (float)NE0;
    int i0 = (int)u0;
    i0 = (i0 < 0) ? 0 : ((i0 > NE0 - 1) ? NE0 - 1 : i0);
    const float f0 = u0 - (float)i0;

    float u1 = sigma * ((float)NE1 * 0.25f);
    int i1 = (int)u1;
    i1 = (i1 < 0) ? 0 : ((i1 > NE1 - 1) ? NE1 - 1 : i1);
    const float f1 = u1 - (float)i1;

    const float4 P = __ldg(&g_patch[i0 * 1024 + i1]);
    const float la = fmaf(f1, P.y - P.x, P.x);
    const float lb = fmaf(f1, P.w - P.z, P.z);
    out[pixel] = fmaf(f0, lb - la, la);
}

// ============================ launch =======================================
extern "C" void kernel_launch(void* const* d_in, const int* in_sizes, int n_in,
                              void* d_out, int out_size)
{
    const float* coords = (const float*)d_in[0];
    const float* cost   = (const float*)d_in[1];
    const float* lsc    = (const float*)d_in[2];
    const float* W1     = (const float*)d_in[3];
    const float* b1     = (const float*)d_in[4];
    const float* W2     = (const float*)d_in[5];
    const float* b2     = (const float*)d_in[6];
    const float* fg     = (const float*)d_in[7];
    const float* fb     = (const float*)d_in[8];
    const float* Wg1    = (const float*)d_in[9];
    const float* bg1    = (const float*)d_in[10];
    const float* Wg2    = (const float*)d_in[11];
    const float* bg2    = (const float*)d_in[12];
    const float* temp   = (const float*)d_in[13];
    const float* lng    = (const float*)d_in[14];
    const float* lnb    = (const float*)d_in[15];
    const float* Wo     = (const float*)d_in[16];
    const float* bo     = (const float*)d_in[17];
    float* out          = (float*)d_out;

    k_nodes<<<NB_TOT + 1, 64>>>(lsc, W1, b1, W2, b2, fg, fb,
                                Wg1, bg1, Wg2, bg2, temp, lng, lnb, Wo, bo);
    k_w2d<<<(65 * 129 + 255) / 256, 256>>>();
    k_out2d<<<64 * 5, 256>>>();
    gnab_main<<<2048, 256>>>(coords, cost, out);
}

// round 17
// speedup vs baseline: 1.3144x; 1.0638x over previous
#include <cuda_runtime.h>
#include <math.h>

// ---------------------------------------------------------------------------
// GatingNeuralAdaptiveBias — output-patch-table form, 3 launches.
//   out(x0, sigma) tabulated as 2x2 float4 PATCHES (256 x 1024, 4MB, L2):
//   main kernel = ONE LDG.128 + bilinear per pixel (2 px/thread for MLP).
//   K1 k_nodes : e0 rows, E1 transposed, [s,q,d] sidecars, coarse gate g rows
//   K2 k_out2d : inline coarse-w0 slice (3x34/block) + X cross-dots +
//                closed-form LN -> float4 patches
//   K3 main    : x0, diamond-sigma -> patch bilinear.
// ---------------------------------------------------------------------------

typedef unsigned int uint;

#define PI_F 3.14159265358979323846f
#define NE0 256
#define NE1 1024
#define NG0 64
#define NG1 128
#define E1TS 1056

__device__ __align__(16) float  g_e0f[260 * 64];
__device__ __align__(16) float  g_e1t[64 * E1TS];
__device__ __align__(16) float  g_s0[260], g_q0[260], g_d0[260];
__device__ __align__(16) float  g_s1[1032], g_q1[1032], g_d1[1032];
__device__ __align__(16) float  g_g0c[68 * 64];
__device__ __align__(16) float  g_g1c[132 * 64];
__device__ __align__(16) float4 g_patch[256 * 1024];    // 4 MB
// g_pre: [0..63] wd ; 64 itemp ; 65 sbw ; 66 bg2d ; 67 c1s
__device__ __align__(16) float g_pre[68];

__device__ __forceinline__ float silu_f(float v) {
    return __fdividef(v, 1.0f + __expf(-v));
}

// theta at a sigma node; sigma in [0,4]; node 0 -> -pi.
__device__ __forceinline__ float theta_from_sigma(float sigma, int ent) {
    if (ent == 0) return -PI_F;
    const float tau = (sigma >= 2.0f) ? sigma - 2.0f : sigma + 2.0f;
    float x, y;
    if      (tau < 1.0f) { x = 1.0f - tau; y = tau; }
    else if (tau < 2.0f) { x = 1.0f - tau; y = 2.0f - tau; }
    else if (tau < 3.0f) { x = tau - 3.0f; y = 2.0f - tau; }
    else                 { x = tau - 3.0f; y = tau - 4.0f; }
    return atan2f(y, x);
}

// ==================== K1: node rows + sidecars + consts ====================
#define NB_E0 257
#define NB_E1 1025
#define NB_G0 65
#define NB_G1 129
#define NB_TOT (NB_E0 + NB_E1 + NB_G0 + NB_G1)   // 1476; grid = 1477
__global__ void __launch_bounds__(64)
k_nodes(const float* __restrict__ lsc,
        const float* __restrict__ W1,  const float* __restrict__ b1,
        const float* __restrict__ W2,  const float* __restrict__ b2,
        const float* __restrict__ fg,  const float* __restrict__ fb,
        const float* __restrict__ Wg1, const float* __restrict__ bg1,
        const float* __restrict__ Wg2, const float* __restrict__ bg2,
        const float* __restrict__ temp,
        const float* __restrict__ lng, const float* __restrict__ lnb,
        const float* __restrict__ Wo,  const float* __restrict__ bo)
{
    const int blk = blockIdx.x;
    const int tid = threadIdx.x;

    if (blk == NB_TOT) {                  // constants
        g_pre[tid] = Wg2[2 * tid] - Wg2[2 * tid + 1];
        if (tid == 0) {
            float s = bo[0], cs = 0.0f;
            for (int k = 0; k < 64; k++) { s += lnb[k] * Wo[k]; cs += lng[k] * Wo[k]; }
            g_pre[64] = expf(-temp[0]);
            g_pre[65] = s;
            g_pre[66] = bg2[0] - bg2[1];
            g_pre[67] = cs;
        }
        return;
    }

    __shared__ float sh[64];
    __shared__ float sred[6];

    int mode, ch, ent;
    if      (blk < NB_E0)                 { mode = 0; ch = 0; ent = blk; }
    else if (blk < NB_E0 + NB_E1)         { mode = 0; ch = 1; ent = blk - NB_E0; }
    else if (blk < NB_E0 + NB_E1 + NB_G0) { mode = 1; ch = 0; ent = blk - NB_E0 - NB_E1; }
    else                                  { mode = 1; ch = 1; ent = blk - NB_E0 - NB_E1 - NB_G0; }

    float x;
    if (ch == 0) x = (float)ent * (mode ? (1.0f / NG0) : (1.0f / NE0));
    else {
        const float sig = (float)ent * (mode ? (4.0f / NG1) : (4.0f / NE1));
        x = theta_from_sigma(sig, ent);
    }
    const float sc = expf(lsc[ch]);

    float ft[9];
    ft[0] = x * sc;
    #pragma unroll
    for (int q = 0; q < 4; q++) {
        float s, c;
        sincosf(x * (float)(1 << q), &s, &c);
        ft[1 + 2 * q] = s * sc;
        ft[2 + 2 * q] = c * sc;
    }

    float z = b1[tid];
    #pragma unroll
    for (int f = 0; f < 9; f++) z = fmaf(ft[f], W1[f * 64 + tid], z);
    sh[tid] = silu_f(z);
    __syncthreads();

    float e = 0.0f;
    #pragma unroll 8
    for (int j = 0; j < 64; j++) e = fmaf(sh[j], W2[j * 64 + tid], e);
    e = fmaf(e + b2[tid], fg[ch * 64 + tid], fb[ch * 64 + tid]);

    if (mode == 0) {
        if (ch) g_e1t[tid * E1TS + ent] = e;       // transposed
        else    g_e0f[ent * 64 + tid]  = e;
        const float c1d = lng[tid] * Wo[tid];
        float s = e, q = e * e, d = e * c1d;
        #pragma unroll
        for (int o = 16; o > 0; o >>= 1) {
            s += __shfl_xor_sync(0xFFFFFFFFu, s, o);
            q += __shfl_xor_sync(0xFFFFFFFFu, q, o);
            d += __shfl_xor_sync(0xFFFFFFFFu, d, o);
        }
        if ((tid & 31) == 0) {
            const int w = tid >> 5;
            sred[w * 3 + 0] = s;  sred[w * 3 + 1] = q;  sred[w * 3 + 2] = d;
        }
        __syncthreads();
        if (tid == 0) {
            if (ch) { g_s1[ent] = sred[0] + sred[3]; g_q1[ent] = sred[1] + sred[4]; g_d1[ent] = sred[2] + sred[5]; }
            else    { g_s0[ent] = sred[0] + sred[3]; g_q0[ent] = sred[1] + sred[4]; g_d0[ent] = sred[2] + sred[5]; }
        }
    } else {
        __syncthreads();
        sh[tid] = e;
        __syncthreads();
        float g = (ch == 0) ? bg1[tid] : 0.0f;
        #pragma unroll 8
        for (int k = 0; k < 64; k++)
            g = fmaf(sh[k], Wg1[(ch * 64 + k) * 64 + tid], g);
        (ch ? g_g1c : g_g0c)[ent * 64 + tid] = g;
    }
}

// ==================== K2: patch build (inline coarse w0) ===================
// grid = 64 row-groups (4 patch-rows, 5 v-rows) x 5 col-segments.
// Warp owns 32 consecutive v-columns -> 31 patches; 8 warps = 248 cols/block.
// Coarse-w0 slice needed per block: rows rg..rg+2, cols seg*31..seg*31+33.
__global__ void __launch_bounds__(256)
k_out2d()
{
    __shared__ __align__(16) float se0[5 * 64];
    __shared__ float sS[15];
    __shared__ float swd[64];
    __shared__ float sw0[3 * 34];

    const int blk = blockIdx.x;
    const int rg  = blk / 5;
    const int seg = blk - rg * 5;
    const int tid = threadIdx.x;
    const int w   = tid >> 5;
    const int lane = tid & 31;

    if (tid < 64) swd[tid] = g_pre[tid];
    for (int t = tid; t < 320; t += 256) {
        const int rr = t >> 6, k = t & 63;
        int i0v = rg * 4 + rr;
        if (i0v > NE0) i0v = NE0;
        se0[t] = g_e0f[i0v * 64 + k];
    }
    if (tid < 5) {
        int i0v = rg * 4 + tid;
        if (i0v > NE0) i0v = NE0;
        sS[tid] = g_s0[i0v];  sS[5 + tid] = g_q0[i0v];  sS[10 + tid] = g_d0[i0v];
    }
    __syncthreads();

    // inline coarse w0 slice: 3 rows x 34 cols
    if (tid < 102) {
        const int r = tid / 34;
        const int c = tid - r * 34;
        int row = rg + r;        if (row > NG0) row = NG0;
        int col = seg * 31 + c;  if (col > NG1) col = NG1;
        const float* a = &g_g0c[row * 64];
        const float* b = &g_g1c[col * 64];
        float acc = g_pre[66];
        #pragma unroll 8
        for (int k = 0; k < 64; k++)
            acc = fmaf(silu_f(a[k] + b[k]), swd[k], acc);
        sw0[tid] = __fdividef(1.0f, 1.0f + __expf(-acc * g_pre[64]));
    }
    __syncthreads();

    const int c  = seg * 248 + w * 31 + lane;      // v-column
    const int cc = (c > NE1) ? NE1 : c;

    float X[5] = {0, 0, 0, 0, 0};
    #pragma unroll 8
    for (int k = 0; k < 64; k++) {
        const float a = __ldg(&g_e1t[k * E1TS + cc]);
        X[0] = fmaf(se0[k],       a, X[0]);
        X[1] = fmaf(se0[64 + k],  a, X[1]);
        X[2] = fmaf(se0[128 + k], a, X[2]);
        X[3] = fmaf(se0[192 + k], a, X[3]);
        X[4] = fmaf(se0[256 + k], a, X[4]);
    }

    const float sbw = g_pre[65];
    const float c1s = g_pre[67];
    const float s1 = g_s1[cc], q1 = g_q1[cc], d1 = g_d1[cc];

    int   i1c = cc >> 3;                            // NE1/NG1 = 8
    float f1c = (float)(cc & 7) * 0.125f;
    if (i1c > NG1 - 1) { i1c = NG1 - 1; f1c = 1.0f; }
    const int lc = i1c - seg * 31;                  // 0..31 (clamped stays >=0)

    float v[5];
    #pragma unroll
    for (int rr = 0; rr < 5; rr++) {
        int i0v = rg * 4 + rr;
        if (i0v > NE0) i0v = NE0;
        int   i0c = i0v >> 2;                       // NE0/NG0 = 4
        float f0c = (float)(i0v & 3) * 0.25f;
        if (i0c > NG0 - 1) { i0c = NG0 - 1; f0c = 1.0f; }
        const int lr = i0c - rg;                    // 0 or 1

        const float t00 = sw0[lr * 34 + lc];
        const float t01 = sw0[lr * 34 + lc + 1];
        const float t10 = sw0[(lr + 1) * 34 + lc];
        const float t11 = sw0[(lr + 1) * 34 + lc + 1];
        const float la = fmaf(f1c, t01 - t00, t00);
        const float lb = fmaf(f1c, t11 - t10, t10);
        const float w0 = fmaf(f0c, lb - la, la);
        const float w1 = 1.0f - w0;

        const float S = w0 * sS[rr] + w1 * s1;
        const float Q = w0 * w0 * sS[5 + rr] + 2.0f * w0 * w1 * X[rr] + w1 * w1 * q1;
        const float D = w0 * sS[10 + rr] + w1 * d1;
        const float mu   = S * (1.0f / 64.0f);
        const float var  = Q * (1.0f / 64.0f) - mu * mu;
        const float rstd = rsqrtf(var + 1e-5f);
        v[rr] = fmaf((D - mu * c1s), rstd, sbw);
    }

    float vn[5];
    #pragma unroll
    for (int rr = 0; rr < 5; rr++)
        vn[rr] = __shfl_down_sync(0xFFFFFFFFu, v[rr], 1);

    if (lane < 31 && c < NE1) {
        const int pr0 = rg * 4;
        #pragma unroll
        for (int rr = 0; rr < 4; rr++) {
            float4 P;
            P.x = v[rr];      P.y = vn[rr];
            P.z = v[rr + 1];  P.w = vn[rr + 1];
            g_patch[(pr0 + rr) * 1024 + c] = P;
        }
    }
}

// ==================== K3: main — 2 pixels/thread patch bilinear ============
__device__ __forceinline__ float patch_eval(float x0, float dx, float dy) {
    const float ax = fabsf(dx), ay = fabsf(dy);
    const float den = ax + ay;
    const float t = (den > 0.0f) ? __fdividef(ay, den) : 0.0f;
    float tau;
    if (dx >= 0.0f) tau = (dy >= 0.0f) ? t : 4.0f - t;
    else            tau = (dy >= 0.0f) ? 2.0f - t : 2.0f + t;
    const float sigma = (tau > 2.0f) ? tau - 2.0f : tau + 2.0f;

    float u0 = x0 * (float)NE0;
    int i0 = (int)u0;
    i0 = (i0 < 0) ? 0 : ((i0 > NE0 - 1) ? NE0 - 1 : i0);
    const float f0 = u0 - (float)i0;

    float u1 = sigma * ((float)NE1 * 0.25f);
    int i1 = (int)u1;
    i1 = (i1 < 0) ? 0 : ((i1 > NE1 - 1) ? NE1 - 1 : i1);
    const float f1 = u1 - (float)i1;

    const float4 P = __ldg(&g_patch[i0 * 1024 + i1]);
    const float la = fmaf(f1, P.y - P.x, P.x);
    const float lb = fmaf(f1, P.w - P.z, P.z);
    return fmaf(f0, lb - la, la);
}

__global__ void __launch_bounds__(256)
gnab_main(const float* __restrict__ coords,
          const float* __restrict__ cost,
          float* __restrict__ out)
{
    const int blk = blockIdx.x;        // covers rows 2*blk, 2*blk+1
    const int j   = threadIdx.x;
    const int r0  = blk * 2;
    const int b   = r0 >> 8;
    const int i0r = r0 & 255;
    const int pxA = r0 * 256 + j;
    const int pxB = pxA + 256;

    const float xA = __ldg(&cost[pxA]);
    const float xB = __ldg(&cost[pxB]);
    const float2 cj  = __ldg(reinterpret_cast<const float2*>(&coords[(b * 256 + j) * 2]));
    const float2 ciA = __ldg(reinterpret_cast<const float2*>(&coords[(b * 256 + i0r) * 2]));
    const float2 ciB = __ldg(reinterpret_cast<const float2*>(&coords[(b * 256 + i0r + 1) * 2]));

    out[pxA] = patch_eval(xA, ciA.x - cj.x, ciA.y - cj.y);
    out[pxB] = patch_eval(xB, ciB.x - cj.x, ciB.y - cj.y);
}

// ============================ launch =======================================
extern "C" void kernel_launch(void* const* d_in, const int* in_sizes, int n_in,
                              void* d_out, int out_size)
{
    const float* coords = (const float*)d_in[0];
    const float* cost   = (const float*)d_in[1];
    const float* lsc    = (const float*)d_in[2];
    const float* W1     = (const float*)d_in[3];
    const float* b1     = (const float*)d_in[4];
    const float* W2     = (const float*)d_in[5];
    const float* b2     = (const float*)d_in[6];
    const float* fg     = (const float*)d_in[7];
    const float* fb     = (const float*)d_in[8];
    const float* Wg1    = (const float*)d_in[9];
    const float* bg1    = (const float*)d_in[10];
    const float* Wg2    = (const float*)d_in[11];
    const float* bg2    = (const float*)d_in[12];
    const float* temp   = (const float*)d_in[13];
    const float* lng    = (const float*)d_in[14];
    const float* lnb    = (const float*)d_in[15];
    const float* Wo     = (const float*)d_in[16];
    const float* bo     = (const float*)d_in[17];
    float* out          = (float*)d_out;

    k_nodes<<<NB_TOT + 1, 64>>>(lsc, W1, b1, W2, b2, fg, fb,
                                Wg1, bg1, Wg2, bg2, temp, lng, lnb, Wo, bo);
    k_out2d<<<64 * 5, 256>>>();
    gnab_main<<<1024, 256>>>(coords, cost, out);
}